// round 1
// baseline (speedup 1.0000x reference)
#include <cuda_runtime.h>
#include <math.h>

#define B_  32
#define T_  2048
#define D_  1024
#define A_  1024

// Scratch (allocation-free: __device__ globals)
__device__ float g_ws[B_ * A_];        // [B, A]  W_a^T s
__device__ float g_scores[B_ * T_];    // [B, T]  raw scores, then exp'd in place
__device__ float g_zinv[B_];           // [B]     1/sum(exp)

// ---------------------------------------------------------------------------
// Kernel 1: ws[b,a] = sum_d s[b,d] * W[d,a]
// grid (A/128, B), block 128
// ---------------------------------------------------------------------------
__global__ __launch_bounds__(128) void ws_kernel(const float* __restrict__ s,
                                                 const float* __restrict__ W) {
    __shared__ float ssm[D_];
    int b = blockIdx.y;
    for (int i = threadIdx.x; i < D_; i += 128) ssm[i] = s[b * D_ + i];
    __syncthreads();

    int a = blockIdx.x * 128 + threadIdx.x;
    float acc = 0.f;
    #pragma unroll 8
    for (int d = 0; d < D_; d++) acc += ssm[d] * W[(size_t)d * A_ + a];
    g_ws[b * A_ + a] = acc;
}

// ---------------------------------------------------------------------------
// Kernel 2 (dominant): score[b,t] = sum_a v[a]*tanh(ws[b,a] + sum_d h[bt,d]*U[d,a])
// Fused tiled GEMM. Block = 64 bt-rows x full A (a-tiles of 64), 256 threads,
// 4x4 micro-tile per thread. T%64==0 so a 64-row tile never crosses a batch.
// grid = B*T/64 = 1024 blocks.
// ---------------------------------------------------------------------------
#define KT 16
__global__ __launch_bounds__(256) void scores_kernel(const float* __restrict__ h,
                                                     const float* __restrict__ U,
                                                     const float* __restrict__ v) {
    const int tile = blockIdx.x;
    const int row0 = tile * 64;            // global bt row base
    const int b    = row0 / T_;
    const float* hbase = h + (size_t)row0 * D_;

    __shared__ float As[KT][68];           // [k][row], padded (bank-safe, 16B aligned)
    __shared__ float Bs[KT][64];           // [k][a]
    __shared__ float wsh[64];
    __shared__ float vsh[64];

    const int tx = threadIdx.x & 15;       // 0..15 -> a cols (x4)
    const int ty = threadIdx.x >> 4;       // 0..15 -> bt rows (x4)

    // gmem staging roles
    const int ar = threadIdx.x >> 2;            // As: row 0..63
    const int ak = (threadIdx.x & 3) * 4;       // As: k group
    const int bk = threadIdx.x >> 4;            // Bs: k 0..15
    const int ba = (threadIdx.x & 15) * 4;      // Bs: a group

    float srow[4] = {0.f, 0.f, 0.f, 0.f};

    for (int a0 = 0; a0 < A_; a0 += 64) {
        __syncthreads();                   // protect wsh/vsh vs previous epilogue readers
        if (threadIdx.x < 64) {
            wsh[threadIdx.x] = g_ws[b * A_ + a0 + threadIdx.x];
            vsh[threadIdx.x] = v[a0 + threadIdx.x];
        }

        float acc[4][4] = {};
        for (int k0 = 0; k0 < D_; k0 += KT) {
            // stage h tile (64 rows x 16 k), transposed into As[k][row]
            float4 hv = *(const float4*)(hbase + (size_t)ar * D_ + k0 + ak);
            // stage U tile (16 k x 64 a)
            float4 uv = *(const float4*)(U + (size_t)(k0 + bk) * A_ + a0 + ba);
            __syncthreads();               // also covers wsh/vsh on first iter
            As[ak + 0][ar] = hv.x; As[ak + 1][ar] = hv.y;
            As[ak + 2][ar] = hv.z; As[ak + 3][ar] = hv.w;
            *(float4*)&Bs[bk][ba] = uv;
            __syncthreads();

            #pragma unroll
            for (int kk = 0; kk < KT; kk++) {
                float4 av = *(const float4*)&As[kk][ty * 4];
                float4 bv = *(const float4*)&Bs[kk][tx * 4];
                acc[0][0] += av.x * bv.x; acc[0][1] += av.x * bv.y;
                acc[0][2] += av.x * bv.z; acc[0][3] += av.x * bv.w;
                acc[1][0] += av.y * bv.x; acc[1][1] += av.y * bv.y;
                acc[1][2] += av.y * bv.z; acc[1][3] += av.y * bv.w;
                acc[2][0] += av.z * bv.x; acc[2][1] += av.z * bv.y;
                acc[2][2] += av.z * bv.z; acc[2][3] += av.z * bv.w;
                acc[3][0] += av.w * bv.x; acc[3][1] += av.w * bv.y;
                acc[3][2] += av.w * bv.z; acc[3][3] += av.w * bv.w;
            }
        }
        __syncthreads();                   // As/Bs done; wsh/vsh stable for epilogue

        // fused epilogue: srow[i] += v[a] * tanh(acc + ws[a])
        #pragma unroll
        for (int j = 0; j < 4; j++) {
            int col = tx * 4 + j;
            float vv = vsh[col];
            float wv = wsh[col];
            #pragma unroll
            for (int i = 0; i < 4; i++)
                srow[i] += vv * tanhf(acc[i][j] + wv);
        }
    }

    // reduce over the 16 tx lanes (lanes with same ty are contiguous in the warp)
    #pragma unroll
    for (int off = 8; off > 0; off >>= 1) {
        #pragma unroll
        for (int i = 0; i < 4; i++)
            srow[i] += __shfl_down_sync(0xffffffffu, srow[i], off);
    }
    if (tx == 0) {
        #pragma unroll
        for (int i = 0; i < 4; i++)
            g_scores[row0 + ty * 4 + i] = srow[i];
    }
}

// ---------------------------------------------------------------------------
// Kernel 3: e = exp(score) in place; zinv[b] = 1/sum_t e  (raw exp, per ref)
// grid B, block 256
// ---------------------------------------------------------------------------
__global__ __launch_bounds__(256) void softmax_kernel() {
    int b = blockIdx.x;
    __shared__ float red[256];
    float sum = 0.f;
    for (int t = threadIdx.x; t < T_; t += 256) {
        float e = expf(g_scores[b * T_ + t]);
        g_scores[b * T_ + t] = e;
        sum += e;
    }
    red[threadIdx.x] = sum;
    __syncthreads();
    for (int s = 128; s > 0; s >>= 1) {
        if (threadIdx.x < s) red[threadIdx.x] += red[threadIdx.x + s];
        __syncthreads();
    }
    if (threadIdx.x == 0) g_zinv[b] = 1.0f / red[0];
}

// ---------------------------------------------------------------------------
// Kernel 4: c[b,d] = zinv[b] * sum_t e[b,t]*h[b,t,d]
// grid (D/128, B), block 128. Coalesced over d; 4 accumulators for MLP.
// ---------------------------------------------------------------------------
__global__ __launch_bounds__(128) void context_kernel(const float* __restrict__ h,
                                                      float* __restrict__ out) {
    int b = blockIdx.y;
    int d = blockIdx.x * 128 + threadIdx.x;
    const float* hb = h + (size_t)b * T_ * D_ + d;
    const float* eb = g_scores + b * T_;

    float a0 = 0.f, a1 = 0.f, a2 = 0.f, a3 = 0.f;
    for (int t = 0; t < T_; t += 4) {
        a0 += eb[t + 0] * hb[(size_t)(t + 0) * D_];
        a1 += eb[t + 1] * hb[(size_t)(t + 1) * D_];
        a2 += eb[t + 2] * hb[(size_t)(t + 2) * D_];
        a3 += eb[t + 3] * hb[(size_t)(t + 3) * D_];
    }
    out[b * D_ + d] = ((a0 + a1) + (a2 + a3)) * g_zinv[b];
}

// ---------------------------------------------------------------------------
extern "C" void kernel_launch(void* const* d_in, const int* in_sizes, int n_in,
                              void* d_out, int out_size) {
    const float* s  = (const float*)d_in[0];   // [B, D]
    const float* h  = (const float*)d_in[1];   // [B, T, D]
    const float* Wa = (const float*)d_in[2];   // [D, A]
    const float* Ua = (const float*)d_in[3];   // [D, A]
    const float* va = (const float*)d_in[4];   // [A]
    float* out = (float*)d_out;                // [B, D]

    ws_kernel<<<dim3(A_ / 128, B_), 128>>>(s, Wa);
    scores_kernel<<<(B_ * T_) / 64, 256>>>(h, Ua, va);
    softmax_kernel<<<B_, 256>>>();
    context_kernel<<<dim3(D_ / 128, B_), 128>>>(h, out);
}

// round 3
// speedup vs baseline: 2.6780x; 2.6780x over previous
#include <cuda_runtime.h>
#include <cstdint>
#include <math.h>

#define B_  32
#define T_  2048
#define D_  1024
#define A_  1024

// ---------------- scratch ---------------------------------------------------
__device__ float g_ws[B_ * A_];
__device__ float g_scores[B_ * T_];
__device__ float g_zinv[B_];
__device__ float g_cpart[8 * B_ * D_];

// ---------------- helpers ---------------------------------------------------
__device__ __forceinline__ uint32_t smem_u32(const void* p) {
    uint32_t a;
    asm("{ .reg .u64 t; cvta.to.shared.u64 t, %1; cvt.u32.u64 %0, t; }" : "=r"(a) : "l"(p));
    return a;
}
__device__ __forceinline__ void cp_async16(uint32_t dst, const void* src) {
    asm volatile("cp.async.cg.shared.global [%0], [%1], 16;\n" :: "r"(dst), "l"(src) : "memory");
}
#define CP_COMMIT() asm volatile("cp.async.commit_group;\n" ::: "memory")
#define CP_WAIT1()  asm volatile("cp.async.wait_group 1;\n" ::: "memory")
#define CP_WAIT0()  asm volatile("cp.async.wait_group 0;\n" ::: "memory")

__device__ __forceinline__ uint32_t f2tf32(float f) {
    uint32_t u;
    asm("cvt.rna.tf32.f32 %0, %1;" : "=r"(u) : "f"(f));
    return u;
}
__device__ __forceinline__ void mma1688(float* c, const uint32_t* a, const uint32_t* b) {
    asm volatile(
        "mma.sync.aligned.m16n8k8.row.col.f32.tf32.tf32.f32 "
        "{%0,%1,%2,%3}, {%4,%5,%6,%7}, {%8,%9}, {%0,%1,%2,%3};"
        : "+f"(c[0]), "+f"(c[1]), "+f"(c[2]), "+f"(c[3])
        : "r"(a[0]), "r"(a[1]), "r"(a[2]), "r"(a[3]), "r"(b[0]), "r"(b[1]));
}

// ---------------- scores kernel smem layout (float words) -------------------
// A stage: 128 rows x 16 k, swizzled 16B chunks            -> 2048 words
// B stage: 16 rows(k) x 128 n + 8 pad words per row        -> 2176 words
#define NSTG   3
#define AS_OFF 0
#define BS_OFF (NSTG * 2048)                 // 6144
#define WS_OFF (BS_OFF + NSTG * 2176)        // 12672
#define VS_OFF (WS_OFF + 1024)               // 13696
#define SC_OFF (VS_OFF + 1024)               // 14720
#define SMEM_WORDS (SC_OFF + 128)            // 14848 -> 59392 bytes

// stage global chunk g (= atile*64 + kstep) into buffer g%NSTG
__device__ __forceinline__ void stage(float* sm, int g, const float* __restrict__ hrow0,
                                      const float* __restrict__ U, int tid) {
    const int sidx = g % NSTG;
    const int k0 = (g & 63) * 16;
    const int a0 = (g >> 6) * 128;
    const uint32_t abase = smem_u32(sm + AS_OFF + sidx * 2048);
    const uint32_t bbase = smem_u32(sm + BS_OFF + sidx * 2176);
    #pragma unroll
    for (int i = 0; i < 2; i++) {
        const int c = tid + i * 256;
        // A: h tile [m][k], chunk swizzle
        const int m = c >> 2, ch = c & 3;
        const uint32_t aw = (uint32_t)(m * 16 + ((ch ^ ((m >> 1) & 3)) << 2));
        cp_async16(abase + aw * 4, hrow0 + (size_t)m * D_ + k0 + ch * 4);
        // B: U tile [k][n], row stride 136 words
        const int k = c >> 5, nc = c & 31;
        const uint32_t bw = (uint32_t)(k * 136 + nc * 4);
        cp_async16(bbase + bw * 4, U + (size_t)(k0 + k) * A_ + a0 + nc * 4);
    }
    CP_COMMIT();
}

// ---------------------------------------------------------------------------
// scores: per CTA 128 bt-rows x full A(1024) x full K(1024).
// 512 chunk-steps of BK=16; epilogue each 64 steps (one a-tile of 128).
// ---------------------------------------------------------------------------
__global__ void __launch_bounds__(256) scores_mma_kernel(const float* __restrict__ h,
                                                         const float* __restrict__ U,
                                                         const float* __restrict__ v) {
    extern __shared__ float sm[];
    const int tid  = threadIdx.x;
    const int lane = tid & 31, wid = tid >> 5;
    const int wm = wid & 3, wn = wid >> 2;     // 4 m-warps x 2 n-warps
    const int g4 = lane >> 2, l4 = lane & 3;
    const int row0 = blockIdx.x * 128;
    const int b = row0 / T_;
    const float* hrow0 = h + (size_t)row0 * D_;

    for (int i = tid; i < 1024; i += 256) {
        sm[WS_OFF + i] = g_ws[b * A_ + i];
        sm[VS_OFF + i] = v[i];
    }
    if (tid < 128) sm[SC_OFF + tid] = 0.f;

    stage(sm, 0, hrow0, U, tid);
    stage(sm, 1, hrow0, U, tid);

    float C[2][8][4];

    for (int g = 0; g < 512; g++) {
        if ((g & 63) == 0) {
            #pragma unroll
            for (int mi = 0; mi < 2; mi++)
                #pragma unroll
                for (int ni = 0; ni < 8; ni++)
                    #pragma unroll
                    for (int q = 0; q < 4; q++) C[mi][ni][q] = 0.f;
        }

        if (g < 511) CP_WAIT1(); else CP_WAIT0();
        __syncthreads();
        if (g + 2 < 512) stage(sm, g + 2, hrow0, U, tid);

        const float* As = sm + AS_OFF + (g % NSTG) * 2048;
        const float* Bs = sm + BS_OFF + (g % NSTG) * 2176;

        #pragma unroll
        for (int k8 = 0; k8 < 2; k8++) {
            const int kb = k8 * 8;
            uint32_t afr[2][4], bfr[8][2];
            #pragma unroll
            for (int mi = 0; mi < 2; mi++) {
                const int rb = wm * 32 + mi * 16 + g4;
                #pragma unroll
                for (int q = 0; q < 4; q++) {
                    const int r = rb + (q & 1) * 8;
                    const int k = kb + l4 + (q >> 1) * 4;
                    afr[mi][q] = f2tf32(As[r * 16 + (((k >> 2) ^ ((r >> 1) & 3)) << 2) + (k & 3)]);
                }
            }
            #pragma unroll
            for (int ni = 0; ni < 8; ni++) {
                const int n = wn * 64 + ni * 8 + g4;
                #pragma unroll
                for (int q = 0; q < 2; q++) {
                    const int k = kb + l4 + q * 4;
                    bfr[ni][q] = f2tf32(Bs[k * 136 + n]);
                }
            }
            #pragma unroll
            for (int mi = 0; mi < 2; mi++)
                #pragma unroll
                for (int ni = 0; ni < 8; ni++)
                    mma1688(C[mi][ni], afr[mi], bfr[ni]);
        }

        if ((g & 63) == 63) {
            // fused epilogue for a-tile at = g>>6
            const int at = g >> 6;
            float racc[2][2] = {{0.f, 0.f}, {0.f, 0.f}};
            #pragma unroll
            for (int ni = 0; ni < 8; ni++) {
                #pragma unroll
                for (int cb = 0; cb < 2; cb++) {
                    const int col = at * 128 + wn * 64 + ni * 8 + l4 * 2 + cb;
                    const float wsv = sm[WS_OFF + col];
                    const float vv  = sm[VS_OFF + col];
                    #pragma unroll
                    for (int mi = 0; mi < 2; mi++) {
                        racc[mi][0] += vv * tanhf(C[mi][ni][cb]     + wsv);
                        racc[mi][1] += vv * tanhf(C[mi][ni][cb + 2] + wsv);
                    }
                }
            }
            #pragma unroll
            for (int off = 1; off <= 2; off <<= 1) {
                #pragma unroll
                for (int mi = 0; mi < 2; mi++) {
                    racc[mi][0] += __shfl_xor_sync(0xffffffffu, racc[mi][0], off);
                    racc[mi][1] += __shfl_xor_sync(0xffffffffu, racc[mi][1], off);
                }
            }
            if (l4 == 0) {
                atomicAdd(&sm[SC_OFF + wm * 32 + g4],      racc[0][0]);
                atomicAdd(&sm[SC_OFF + wm * 32 + g4 + 8],  racc[0][1]);
                atomicAdd(&sm[SC_OFF + wm * 32 + 16 + g4], racc[1][0]);
                atomicAdd(&sm[SC_OFF + wm * 32 + 24 + g4], racc[1][1]);
            }
        }
    }

    __syncthreads();
    if (tid < 128) g_scores[row0 + tid] = sm[SC_OFF + tid];
}

// ---------------------------------------------------------------------------
__global__ __launch_bounds__(128) void ws_kernel(const float* __restrict__ s,
                                                 const float* __restrict__ W) {
    __shared__ float ssm[D_];
    int b = blockIdx.y;
    for (int i = threadIdx.x; i < D_; i += 128) ssm[i] = s[b * D_ + i];
    __syncthreads();
    int a = blockIdx.x * 128 + threadIdx.x;
    float acc = 0.f;
    #pragma unroll 8
    for (int d = 0; d < D_; d++) acc += ssm[d] * W[(size_t)d * A_ + a];
    g_ws[b * A_ + a] = acc;
}

__global__ __launch_bounds__(256) void softmax_kernel() {
    int b = blockIdx.x;
    __shared__ float red[256];
    float sum = 0.f;
    for (int t = threadIdx.x; t < T_; t += 256) {
        float e = expf(g_scores[b * T_ + t]);
        g_scores[b * T_ + t] = e;
        sum += e;
    }
    red[threadIdx.x] = sum;
    __syncthreads();
    for (int s = 128; s > 0; s >>= 1) {
        if (threadIdx.x < s) red[threadIdx.x] += red[threadIdx.x + s];
        __syncthreads();
    }
    if (threadIdx.x == 0) g_zinv[b] = 1.0f / red[0];
}

__global__ __launch_bounds__(128) void context_part_kernel(const float* __restrict__ h) {
    int b = blockIdx.y, tc = blockIdx.z;
    int d = blockIdx.x * 128 + threadIdx.x;
    const float* hb = h + (size_t)b * T_ * D_ + (size_t)tc * 256 * D_ + d;
    const float* eb = g_scores + b * T_ + tc * 256;
    float a0 = 0.f, a1 = 0.f, a2 = 0.f, a3 = 0.f;
    for (int t = 0; t < 256; t += 4) {
        a0 += eb[t + 0] * hb[(size_t)(t + 0) * D_];
        a1 += eb[t + 1] * hb[(size_t)(t + 1) * D_];
        a2 += eb[t + 2] * hb[(size_t)(t + 2) * D_];
        a3 += eb[t + 3] * hb[(size_t)(t + 3) * D_];
    }
    g_cpart[((size_t)tc * B_ + b) * D_ + d] = ((a0 + a1) + (a2 + a3));
}

__global__ __launch_bounds__(256) void context_reduce_kernel(float* __restrict__ out) {
    int idx = blockIdx.x * 256 + threadIdx.x;
    float sum = 0.f;
    #pragma unroll
    for (int z = 0; z < 8; z++) sum += g_cpart[(size_t)z * B_ * D_ + idx];
    out[idx] = sum * g_zinv[idx >> 10];
}

// ---------------------------------------------------------------------------
extern "C" void kernel_launch(void* const* d_in, const int* in_sizes, int n_in,
                              void* d_out, int out_size) {
    const float* s  = (const float*)d_in[0];
    const float* h  = (const float*)d_in[1];
    const float* Wa = (const float*)d_in[2];
    const float* Ua = (const float*)d_in[3];
    const float* va = (const float*)d_in[4];
    float* out = (float*)d_out;

    cudaFuncSetAttribute(scores_mma_kernel,
                         cudaFuncAttributeMaxDynamicSharedMemorySize, SMEM_WORDS * 4);

    ws_kernel<<<dim3(A_ / 128, B_), 128>>>(s, Wa);
    scores_mma_kernel<<<(B_ * T_) / 128, 256, SMEM_WORDS * 4>>>(h, Ua, va);
    softmax_kernel<<<B_, 256>>>();
    context_part_kernel<<<dim3(D_ / 128, B_, 8), 128>>>(h);
    context_reduce_kernel<<<128, 256>>>(out);
}

// round 6
// speedup vs baseline: 5.6618x; 2.1142x over previous
#include <cuda_runtime.h>
#include <cuda_fp16.h>
#include <cstdint>
#include <math.h>

#define B_  32
#define T_  2048
#define D_  1024
#define A_  1024

// ---------------- scratch ---------------------------------------------------
__device__ float  g_ws[B_ * A_];
__device__ float  g_scores[B_ * T_];
__device__ float  g_zinv[B_];
__device__ float  g_cpart[8 * B_ * D_];
__device__ __half g_h16[(size_t)B_ * T_ * D_];   // 128 MB
__device__ __half g_U16[(size_t)D_ * A_];        // 2 MB

// ---------------- helpers ---------------------------------------------------
__device__ __forceinline__ uint32_t smem_u32(const void* p) {
    uint32_t a;
    asm("{ .reg .u64 t; cvta.to.shared.u64 t, %1; cvt.u32.u64 %0, t; }" : "=r"(a) : "l"(p));
    return a;
}
__device__ __forceinline__ void cp_async16(uint32_t dst, const void* src) {
    asm volatile("cp.async.cg.shared.global [%0], [%1], 16;\n" :: "r"(dst), "l"(src) : "memory");
}
#define CP_COMMIT() asm volatile("cp.async.commit_group;\n" ::: "memory")
#define CP_WAIT1()  asm volatile("cp.async.wait_group 1;\n" ::: "memory")
#define CP_WAIT0()  asm volatile("cp.async.wait_group 0;\n" ::: "memory")

__device__ __forceinline__ void ldsm_x4(uint32_t* r, uint32_t addr) {
    asm volatile("ldmatrix.sync.aligned.m8n8.x4.shared.b16 {%0,%1,%2,%3}, [%4];"
        : "=r"(r[0]), "=r"(r[1]), "=r"(r[2]), "=r"(r[3]) : "r"(addr));
}
__device__ __forceinline__ void ldsm_x4_t(uint32_t* r, uint32_t addr) {
    asm volatile("ldmatrix.sync.aligned.m8n8.x4.trans.shared.b16 {%0,%1,%2,%3}, [%4];"
        : "=r"(r[0]), "=r"(r[1]), "=r"(r[2]), "=r"(r[3]) : "r"(addr));
}
__device__ __forceinline__ void mma16816(float* c, const uint32_t* a, const uint32_t* b) {
    asm volatile(
        "mma.sync.aligned.m16n8k16.row.col.f32.f16.f16.f32 "
        "{%0,%1,%2,%3}, {%4,%5,%6,%7}, {%8,%9}, {%0,%1,%2,%3};"
        : "+f"(c[0]), "+f"(c[1]), "+f"(c[2]), "+f"(c[3])
        : "r"(a[0]), "r"(a[1]), "r"(a[2]), "r"(a[3]), "r"(b[0]), "r"(b[1]));
}

// ---------------- smem layout (bytes) ---------------------------------------
// A stage: 128 m-rows, stride 112 B (32 fp16 data + pad) -> 14336 B
//          ldmatrix row phases: 7k mod 8 -> all distinct -> conflict-free
// B stage: 32 k-rows, stride 272 B (128 fp16 data + pad) -> 8704 B
//          ldmatrix row phases: 17k mod 8 = k mod 8 -> conflict-free
#define NSTG     3
#define A_STRIDE 112
#define B_STRIDE 272
#define ASTG_SZ  (128 * A_STRIDE)                // 14336
#define BSTG_SZ  (32 * B_STRIDE)                 // 8704
#define AS_OFF   0
#define BS_OFF   (NSTG * ASTG_SZ)                // 43008
#define WS_OFF   (BS_OFF + NSTG * BSTG_SZ)       // 69120
#define VS_OFF   (WS_OFF + 4096)                 // 73216
#define SC_OFF   (VS_OFF + 4096)                 // 77312
#define SMEM_SZ  (SC_OFF + 512)                  // 77824

// total g-steps: 8 a-tiles x 32 k-chunks = 256  (THE R4/R5 BUG: was 128)
#define NG 256

// stage chunk g = at*32 + kc: A tile (kc), B tile (at, kc). No swizzle.
__device__ __forceinline__ void stage(char* sm, int g, const __half* __restrict__ h16row0,
                                      int tid) {
    const int sidx = g % NSTG;
    const int kc = g & 31, at = g >> 5;
    const int k0 = kc * 32;
    const uint32_t abase = smem_u32(sm + AS_OFF + sidx * ASTG_SZ);
    const uint32_t bbase = smem_u32(sm + BS_OFF + sidx * BSTG_SZ);
    const __half* bsrc = g_U16 + (size_t)k0 * A_ + at * 128;
    #pragma unroll
    for (int i = 0; i < 2; i++) {
        const int q = tid + i * 256;             // 0..511
        // A: m = q>>2, 16B chunk c = q&3
        const int m = q >> 2, c = q & 3;
        cp_async16(abase + (uint32_t)(m * A_STRIDE + c * 16),
                   h16row0 + (size_t)m * D_ + k0 + c * 8);
        // B: k = q>>4, 16B n-chunk nc = q&15
        const int k = q >> 4, nc = q & 15;
        cp_async16(bbase + (uint32_t)(k * B_STRIDE + nc * 16),
                   bsrc + (size_t)k * A_ + nc * 8);
    }
    CP_COMMIT();
}

// ---------------------------------------------------------------------------
// scores: CTA = 128 bt-rows x A(1024) x K(1024). 256 g-steps of BK=32;
// fused tanh+v-dot epilogue every 32 steps (one 128-wide a-tile).
// ---------------------------------------------------------------------------
__global__ void __launch_bounds__(256) scores_mma_kernel(const float* __restrict__ v) {
    extern __shared__ char smc[];
    const int tid  = threadIdx.x;
    const int lane = tid & 31, wid = tid >> 5;
    const int wm = wid & 3, wn = wid >> 2;        // 4 m-warps x 2 n-warps
    const int g4 = lane >> 2, l4 = lane & 3;
    const int row0 = blockIdx.x * 128;
    const int b = row0 / T_;
    const __half* h16row0 = g_h16 + (size_t)row0 * D_;

    float* wsh = (float*)(smc + WS_OFF);
    float* vsh = (float*)(smc + VS_OFF);
    float* sch = (float*)(smc + SC_OFF);

    for (int i = tid; i < 1024; i += 256) {
        wsh[i] = g_ws[b * A_ + i];
        vsh[i] = v[i];
    }
    if (tid < 128) sch[tid] = 0.f;

    // ldmatrix lane roles (canonical x4):
    //   lanes 0-7:   rows 0-7  of tile, chunk 0   (matrix 0)
    //   lanes 8-15:  rows 8-15 of tile, chunk 0   (matrix 1)
    //   lanes 16-23: rows 0-7  of tile, chunk 1   (matrix 2)
    //   lanes 24-31: rows 8-15 of tile, chunk 1   (matrix 3)
    const int frow  = (lane & 7) + ((lane >> 3) & 1) * 8;
    const int chalf = (lane >> 4) & 1;
    uint32_t a_rowoff[2];
    #pragma unroll
    for (int mi = 0; mi < 2; mi++)
        a_rowoff[mi] = (uint32_t)((wm * 32 + mi * 16 + frow) * A_STRIDE);

    stage(smc, 0, h16row0, tid);
    stage(smc, 1, h16row0, tid);

    float C[2][8][4];

    for (int g = 0; g < NG; g++) {
        if ((g & 31) == 0) {
            #pragma unroll
            for (int mi = 0; mi < 2; mi++)
                #pragma unroll
                for (int ni = 0; ni < 8; ni++)
                    #pragma unroll
                    for (int q = 0; q < 4; q++) C[mi][ni][q] = 0.f;
        }

        if (g < NG - 2) CP_WAIT1(); else CP_WAIT0();
        __syncthreads();
        if (g + 2 < NG) stage(smc, g + 2, h16row0, tid);

        const uint32_t abase = smem_u32(smc + AS_OFF + (g % NSTG) * ASTG_SZ);
        const uint32_t bbase = smem_u32(smc + BS_OFF + (g % NSTG) * BSTG_SZ);

        #pragma unroll
        for (int ks = 0; ks < 32; ks += 16) {
            uint32_t afr[2][4];
            const uint32_t acol = (uint32_t)(((ks >> 3) + chalf) * 16);
            #pragma unroll
            for (int mi = 0; mi < 2; mi++)
                ldsm_x4(afr[mi], abase + a_rowoff[mi] + acol);

            const uint32_t brow = bbase + (uint32_t)((ks + frow) * B_STRIDE);
            #pragma unroll
            for (int p = 0; p < 4; p++) {
                uint32_t bfr[4];
                const uint32_t bcol = (uint32_t)((wn * 8 + p * 2 + chalf) * 16);
                ldsm_x4_t(bfr, brow + bcol);
                mma16816(C[0][p * 2],     afr[0], bfr);
                mma16816(C[0][p * 2 + 1], afr[0], bfr + 2);
                mma16816(C[1][p * 2],     afr[1], bfr);
                mma16816(C[1][p * 2 + 1], afr[1], bfr + 2);
            }
        }

        if ((g & 31) == 31) {
            const int at = g >> 5;                 // 0..7: full A coverage
            float racc[2][2] = {{0.f, 0.f}, {0.f, 0.f}};
            #pragma unroll
            for (int ni = 0; ni < 8; ni++) {
                #pragma unroll
                for (int cb = 0; cb < 2; cb++) {
                    const int col = at * 128 + wn * 64 + ni * 8 + l4 * 2 + cb;
                    const float wsv = wsh[col];
                    const float vv  = vsh[col];
                    #pragma unroll
                    for (int mi = 0; mi < 2; mi++) {
                        racc[mi][0] += vv * tanhf(C[mi][ni][cb]     + wsv);
                        racc[mi][1] += vv * tanhf(C[mi][ni][cb + 2] + wsv);
                    }
                }
            }
            #pragma unroll
            for (int off = 1; off <= 2; off <<= 1) {
                #pragma unroll
                for (int mi = 0; mi < 2; mi++) {
                    racc[mi][0] += __shfl_xor_sync(0xffffffffu, racc[mi][0], off);
                    racc[mi][1] += __shfl_xor_sync(0xffffffffu, racc[mi][1], off);
                }
            }
            if (l4 == 0) {
                atomicAdd(&sch[wm * 32 + g4],      racc[0][0]);
                atomicAdd(&sch[wm * 32 + g4 + 8],  racc[0][1]);
                atomicAdd(&sch[wm * 32 + 16 + g4], racc[1][0]);
                atomicAdd(&sch[wm * 32 + 24 + g4], racc[1][1]);
            }
        }
    }

    __syncthreads();
    if (tid < 128) g_scores[row0 + tid] = sch[tid];
}

// ---------------------------------------------------------------------------
// fp32 -> fp16 converters
// ---------------------------------------------------------------------------
__global__ __launch_bounds__(256) void conv_h_kernel(const float* __restrict__ h) {
    const size_t i = (size_t)blockIdx.x * 256 + threadIdx.x;   // float4 index
    const float4 val = ((const float4*)h)[i];
    __half2 lo = __floats2half2_rn(val.x, val.y);
    __half2 hi = __floats2half2_rn(val.z, val.w);
    ((uint2*)g_h16)[i] = make_uint2(*(uint32_t*)&lo, *(uint32_t*)&hi);
}
__global__ __launch_bounds__(256) void conv_U_kernel(const float* __restrict__ U) {
    const size_t i = (size_t)blockIdx.x * 256 + threadIdx.x;
    const float4 val = ((const float4*)U)[i];
    __half2 lo = __floats2half2_rn(val.x, val.y);
    __half2 hi = __floats2half2_rn(val.z, val.w);
    ((uint2*)g_U16)[i] = make_uint2(*(uint32_t*)&lo, *(uint32_t*)&hi);
}

// ---------------------------------------------------------------------------
__global__ __launch_bounds__(128) void ws_kernel(const float* __restrict__ s,
                                                 const float* __restrict__ W) {
    __shared__ float ssm[D_];
    int b = blockIdx.y;
    for (int i = threadIdx.x; i < D_; i += 128) ssm[i] = s[b * D_ + i];
    __syncthreads();
    int a = blockIdx.x * 128 + threadIdx.x;
    float acc = 0.f;
    #pragma unroll 8
    for (int d = 0; d < D_; d++) acc += ssm[d] * W[(size_t)d * A_ + a];
    g_ws[b * A_ + a] = acc;
}

__global__ __launch_bounds__(256) void softmax_kernel() {
    int b = blockIdx.x;
    __shared__ float red[256];
    float sum = 0.f;
    for (int t = threadIdx.x; t < T_; t += 256) {
        float e = expf(g_scores[b * T_ + t]);
        g_scores[b * T_ + t] = e;
        sum += e;
    }
    red[threadIdx.x] = sum;
    __syncthreads();
    for (int s = 128; s > 0; s >>= 1) {
        if (threadIdx.x < s) red[threadIdx.x] += red[threadIdx.x + s];
        __syncthreads();
    }
    if (threadIdx.x == 0) g_zinv[b] = 1.0f / red[0];
}

__global__ __launch_bounds__(128) void context_part_kernel(const float* __restrict__ h) {
    int b = blockIdx.y, tc = blockIdx.z;
    int d = blockIdx.x * 128 + threadIdx.x;
    const float* hb = h + (size_t)b * T_ * D_ + (size_t)tc * 256 * D_ + d;
    const float* eb = g_scores + b * T_ + tc * 256;
    float a0 = 0.f, a1 = 0.f, a2 = 0.f, a3 = 0.f;
    #pragma unroll 2
    for (int t = 0; t < 256; t += 4) {
        a0 += eb[t + 0] * hb[(size_t)(t + 0) * D_];
        a1 += eb[t + 1] * hb[(size_t)(t + 1) * D_];
        a2 += eb[t + 2] * hb[(size_t)(t + 2) * D_];
        a3 += eb[t + 3] * hb[(size_t)(t + 3) * D_];
    }
    g_cpart[((size_t)tc * B_ + b) * D_ + d] = ((a0 + a1) + (a2 + a3));
}

__global__ __launch_bounds__(256) void context_reduce_kernel(float* __restrict__ out) {
    int idx = blockIdx.x * 256 + threadIdx.x;
    float sum = 0.f;
    #pragma unroll
    for (int z = 0; z < 8; z++) sum += g_cpart[(size_t)z * B_ * D_ + idx];
    out[idx] = sum * g_zinv[idx >> 10];
}

// ---------------------------------------------------------------------------
extern "C" void kernel_launch(void* const* d_in, const int* in_sizes, int n_in,
                              void* d_out, int out_size) {
    const float* s  = (const float*)d_in[0];
    const float* h  = (const float*)d_in[1];
    const float* Wa = (const float*)d_in[2];
    const float* Ua = (const float*)d_in[3];
    const float* va = (const float*)d_in[4];
    float* out = (float*)d_out;

    cudaFuncSetAttribute(scores_mma_kernel,
                         cudaFuncAttributeMaxDynamicSharedMemorySize, SMEM_SZ);

    conv_U_kernel<<<(D_ * A_ / 4) / 256, 256>>>(Ua);
    conv_h_kernel<<<(int)(((size_t)B_ * T_ * D_ / 4) / 256), 256>>>(h);
    ws_kernel<<<dim3(A_ / 128, B_), 128>>>(s, Wa);
    scores_mma_kernel<<<(B_ * T_) / 128, 256, SMEM_SZ>>>(va);
    softmax_kernel<<<B_, 256>>>();
    context_part_kernel<<<dim3(D_ / 128, B_, 8), 128>>>(h);
    context_reduce_kernel<<<128, 256>>>(out);
}

// round 7
// speedup vs baseline: 5.7826x; 1.0213x over previous
#include <cuda_runtime.h>
#include <cuda_fp16.h>
#include <cstdint>
#include <math.h>

#define B_  32
#define T_  2048
#define D_  1024
#define A_  1024

// ---------------- scratch ---------------------------------------------------
__device__ float  g_ws[B_ * A_];
__device__ float  g_scores[B_ * T_];
__device__ float  g_zinv[B_];
__device__ float  g_cpart[16 * B_ * D_];
__device__ __half g_h16[(size_t)B_ * T_ * D_];   // 128 MB
__device__ __half g_U16[(size_t)D_ * A_];        // 2 MB

// ---------------- helpers ---------------------------------------------------
__device__ __forceinline__ uint32_t smem_u32(const void* p) {
    uint32_t a;
    asm("{ .reg .u64 t; cvta.to.shared.u64 t, %1; cvt.u32.u64 %0, t; }" : "=r"(a) : "l"(p));
    return a;
}
__device__ __forceinline__ void cp_async16(uint32_t dst, const void* src) {
    asm volatile("cp.async.cg.shared.global [%0], [%1], 16;\n" :: "r"(dst), "l"(src) : "memory");
}
#define CP_COMMIT() asm volatile("cp.async.commit_group;\n" ::: "memory")
#define CP_WAIT2()  asm volatile("cp.async.wait_group 2;\n" ::: "memory")
#define CP_WAIT1()  asm volatile("cp.async.wait_group 1;\n" ::: "memory")
#define CP_WAIT0()  asm volatile("cp.async.wait_group 0;\n" ::: "memory")

__device__ __forceinline__ void ldsm_x4(uint32_t* r, uint32_t addr) {
    asm volatile("ldmatrix.sync.aligned.m8n8.x4.shared.b16 {%0,%1,%2,%3}, [%4];"
        : "=r"(r[0]), "=r"(r[1]), "=r"(r[2]), "=r"(r[3]) : "r"(addr));
}
__device__ __forceinline__ void ldsm_x4_t(uint32_t* r, uint32_t addr) {
    asm volatile("ldmatrix.sync.aligned.m8n8.x4.trans.shared.b16 {%0,%1,%2,%3}, [%4];"
        : "=r"(r[0]), "=r"(r[1]), "=r"(r[2]), "=r"(r[3]) : "r"(addr));
}
__device__ __forceinline__ void mma16816(float* c, const uint32_t* a, const uint32_t* b) {
    asm volatile(
        "mma.sync.aligned.m16n8k16.row.col.f32.f16.f16.f32 "
        "{%0,%1,%2,%3}, {%4,%5,%6,%7}, {%8,%9}, {%0,%1,%2,%3};"
        : "+f"(c[0]), "+f"(c[1]), "+f"(c[2]), "+f"(c[3])
        : "r"(a[0]), "r"(a[1]), "r"(a[2]), "r"(a[3]), "r"(b[0]), "r"(b[1]));
}

// ---------------- smem layout (bytes) ---------------------------------------
// A stage: 128 m-rows, stride 112 B  (7k mod 8 phases -> conflict-free)
// B stage: 32 k-rows,  stride 272 B  (17k mod 8 = k mod 8 -> conflict-free)
#define NSTG     4
#define A_STRIDE 112
#define B_STRIDE 272
#define ASTG_SZ  (128 * A_STRIDE)                // 14336
#define BSTG_SZ  (32 * B_STRIDE)                 // 8704
#define AS_OFF   0
#define BS_OFF   (NSTG * ASTG_SZ)                // 57344
#define WS_OFF   (BS_OFF + NSTG * BSTG_SZ)       // 92160
#define VS_OFF   (WS_OFF + 4096)                 // 96256
#define SC_OFF   (VS_OFF + 4096)                 // 100352  (2 banks x 128 floats)
#define SMEM_SZ  (SC_OFF + 1024)                 // 101376

#define NG 256   // 8 a-tiles x 32 k-chunks

// stage chunk g = at*32 + kc
__device__ __forceinline__ void stage(char* sm, int g, const __half* __restrict__ h16row0,
                                      int tid) {
    const int sidx = g % NSTG;
    const int kc = g & 31, at = g >> 5;
    const int k0 = kc * 32;
    const uint32_t abase = smem_u32(sm + AS_OFF + sidx * ASTG_SZ);
    const uint32_t bbase = smem_u32(sm + BS_OFF + sidx * BSTG_SZ);
    const __half* bsrc = g_U16 + (size_t)k0 * A_ + at * 128;
    #pragma unroll
    for (int i = 0; i < 2; i++) {
        const int q = tid + i * 256;             // 0..511
        const int m = q >> 2, c = q & 3;
        cp_async16(abase + (uint32_t)(m * A_STRIDE + c * 16),
                   h16row0 + (size_t)m * D_ + k0 + c * 8);
        const int k = q >> 4, nc = q & 15;
        cp_async16(bbase + (uint32_t)(k * B_STRIDE + nc * 16),
                   bsrc + (size_t)k * A_ + nc * 8);
    }
    CP_COMMIT();
}

// ---------------------------------------------------------------------------
// scores: CTA = 128 bt-rows x A(1024) x K(1024). 256 g-steps of BK=32;
// 4-stage pipeline, stage-distance 3, wait_group 2.
// ---------------------------------------------------------------------------
__global__ void __launch_bounds__(256, 2) scores_mma_kernel(const float* __restrict__ v) {
    extern __shared__ char smc[];
    const int tid  = threadIdx.x;
    const int lane = tid & 31, wid = tid >> 5;
    const int wm = wid & 3, wn = wid >> 2;        // 4 m-warps x 2 n-warps
    const int g4 = lane >> 2, l4 = lane & 3;
    const int row0 = blockIdx.x * 128;
    const int b = row0 / T_;
    const __half* h16row0 = g_h16 + (size_t)row0 * D_;

    float* wsh = (float*)(smc + WS_OFF);
    float* vsh = (float*)(smc + VS_OFF);
    float* sch = (float*)(smc + SC_OFF);          // [2][128], bank per wn

    for (int i = tid; i < 1024; i += 256) {
        wsh[i] = g_ws[b * A_ + i];
        vsh[i] = v[i];
    }
    sch[tid] = 0.f;                               // 256 entries

    const int frow  = (lane & 7) + ((lane >> 3) & 1) * 8;
    const int chalf = (lane >> 4) & 1;
    uint32_t a_rowoff[2];
    #pragma unroll
    for (int mi = 0; mi < 2; mi++)
        a_rowoff[mi] = (uint32_t)((wm * 32 + mi * 16 + frow) * A_STRIDE);

    stage(smc, 0, h16row0, tid);
    stage(smc, 1, h16row0, tid);
    stage(smc, 2, h16row0, tid);

    float C[2][8][4];

    for (int g = 0; g < NG; g++) {
        if ((g & 31) == 0) {
            #pragma unroll
            for (int mi = 0; mi < 2; mi++)
                #pragma unroll
                for (int ni = 0; ni < 8; ni++)
                    #pragma unroll
                    for (int q = 0; q < 4; q++) C[mi][ni][q] = 0.f;
        }

        // ensure chunk g resident: pending groups beyond g = min(2, NG-1-g)
        if (g <= NG - 3)      CP_WAIT2();
        else if (g == NG - 2) CP_WAIT1();
        else                  CP_WAIT0();
        __syncthreads();
        if (g + 3 < NG) stage(smc, g + 3, h16row0, tid);

        const uint32_t abase = smem_u32(smc + AS_OFF + (g % NSTG) * ASTG_SZ);
        const uint32_t bbase = smem_u32(smc + BS_OFF + (g % NSTG) * BSTG_SZ);

        #pragma unroll
        for (int ks = 0; ks < 32; ks += 16) {
            uint32_t afr[2][4];
            const uint32_t acol = (uint32_t)(((ks >> 3) + chalf) * 16);
            #pragma unroll
            for (int mi = 0; mi < 2; mi++)
                ldsm_x4(afr[mi], abase + a_rowoff[mi] + acol);

            const uint32_t brow = bbase + (uint32_t)((ks + frow) * B_STRIDE);
            #pragma unroll
            for (int p = 0; p < 4; p++) {
                uint32_t bfr[4];
                const uint32_t bcol = (uint32_t)((wn * 8 + p * 2 + chalf) * 16);
                ldsm_x4_t(bfr, brow + bcol);
                mma16816(C[0][p * 2],     afr[0], bfr);
                mma16816(C[0][p * 2 + 1], afr[0], bfr + 2);
                mma16816(C[1][p * 2],     afr[1], bfr);
                mma16816(C[1][p * 2 + 1], afr[1], bfr + 2);
            }
        }

        if ((g & 31) == 31) {
            const int at = g >> 5;
            float racc[2][2] = {{0.f, 0.f}, {0.f, 0.f}};
            #pragma unroll
            for (int ni = 0; ni < 8; ni++) {
                #pragma unroll
                for (int cb = 0; cb < 2; cb++) {
                    const int col = at * 128 + wn * 64 + ni * 8 + l4 * 2 + cb;
                    const float wsv = wsh[col];
                    const float vv  = vsh[col];
                    #pragma unroll
                    for (int mi = 0; mi < 2; mi++) {
                        racc[mi][0] += vv * tanhf(C[mi][ni][cb]     + wsv);
                        racc[mi][1] += vv * tanhf(C[mi][ni][cb + 2] + wsv);
                    }
                }
            }
            #pragma unroll
            for (int off = 1; off <= 2; off <<= 1) {
                #pragma unroll
                for (int mi = 0; mi < 2; mi++) {
                    racc[mi][0] += __shfl_xor_sync(0xffffffffu, racc[mi][0], off);
                    racc[mi][1] += __shfl_xor_sync(0xffffffffu, racc[mi][1], off);
                }
            }
            // each address owned by exactly one (wn, wm, g4) thread: plain +=
            if (l4 == 0) {
                float* bank = sch + wn * 128 + wm * 32;
                bank[g4]      += racc[0][0];
                bank[g4 + 8]  += racc[0][1];
                bank[g4 + 16] += racc[1][0];
                bank[g4 + 24] += racc[1][1];
            }
        }
    }

    __syncthreads();
    if (tid < 128) g_scores[row0 + tid] = sch[tid] + sch[128 + tid];
}

// ---------------------------------------------------------------------------
// fp32 -> fp16 converters
// ---------------------------------------------------------------------------
__global__ __launch_bounds__(256) void conv_h_kernel(const float* __restrict__ h) {
    const size_t i = (size_t)blockIdx.x * 256 + threadIdx.x;
    const float4 val = ((const float4*)h)[i];
    __half2 lo = __floats2half2_rn(val.x, val.y);
    __half2 hi = __floats2half2_rn(val.z, val.w);
    ((uint2*)g_h16)[i] = make_uint2(*(uint32_t*)&lo, *(uint32_t*)&hi);
}
__global__ __launch_bounds__(256) void conv_U_kernel(const float* __restrict__ U) {
    const size_t i = (size_t)blockIdx.x * 256 + threadIdx.x;
    const float4 val = ((const float4*)U)[i];
    __half2 lo = __floats2half2_rn(val.x, val.y);
    __half2 hi = __floats2half2_rn(val.z, val.w);
    ((uint2*)g_U16)[i] = make_uint2(*(uint32_t*)&lo, *(uint32_t*)&hi);
}

// ---------------------------------------------------------------------------
__global__ __launch_bounds__(128) void ws_kernel(const float* __restrict__ s,
                                                 const float* __restrict__ W) {
    __shared__ float ssm[D_];
    int b = blockIdx.y;
    for (int i = threadIdx.x; i < D_; i += 128) ssm[i] = s[b * D_ + i];
    __syncthreads();
    int a = blockIdx.x * 128 + threadIdx.x;
    float acc = 0.f;
    #pragma unroll 8
    for (int d = 0; d < D_; d++) acc += ssm[d] * W[(size_t)d * A_ + a];
    g_ws[b * A_ + a] = acc;
}

__global__ __launch_bounds__(256) void softmax_kernel() {
    int b = blockIdx.x;
    __shared__ float red[256];
    float sum = 0.f;
    for (int t = threadIdx.x; t < T_; t += 256) {
        float e = expf(g_scores[b * T_ + t]);
        g_scores[b * T_ + t] = e;
        sum += e;
    }
    red[threadIdx.x] = sum;
    __syncthreads();
    for (int s = 128; s > 0; s >>= 1) {
        if (threadIdx.x < s) red[threadIdx.x] += red[threadIdx.x + s];
        __syncthreads();
    }
    if (threadIdx.x == 0) g_zinv[b] = 1.0f / red[0];
}

// 16-way t-split: grid (D/128, B, 16)
__global__ __launch_bounds__(128) void context_part_kernel(const float* __restrict__ h) {
    int b = blockIdx.y, tc = blockIdx.z;
    int d = blockIdx.x * 128 + threadIdx.x;
    const float* hb = h + (size_t)b * T_ * D_ + (size_t)tc * 128 * D_ + d;
    const float* eb = g_scores + b * T_ + tc * 128;
    float a0 = 0.f, a1 = 0.f, a2 = 0.f, a3 = 0.f;
    #pragma unroll 2
    for (int t = 0; t < 128; t += 4) {
        a0 += eb[t + 0] * hb[(size_t)(t + 0) * D_];
        a1 += eb[t + 1] * hb[(size_t)(t + 1) * D_];
        a2 += eb[t + 2] * hb[(size_t)(t + 2) * D_];
        a3 += eb[t + 3] * hb[(size_t)(t + 3) * D_];
    }
    g_cpart[((size_t)tc * B_ + b) * D_ + d] = ((a0 + a1) + (a2 + a3));
}

__global__ __launch_bounds__(256) void context_reduce_kernel(float* __restrict__ out) {
    int idx = blockIdx.x * 256 + threadIdx.x;
    float sum = 0.f;
    #pragma unroll
    for (int z = 0; z < 16; z++) sum += g_cpart[(size_t)z * B_ * D_ + idx];
    out[idx] = sum * g_zinv[idx >> 10];
}

// ---------------------------------------------------------------------------
extern "C" void kernel_launch(void* const* d_in, const int* in_sizes, int n_in,
                              void* d_out, int out_size) {
    const float* s  = (const float*)d_in[0];
    const float* h  = (const float*)d_in[1];
    const float* Wa = (const float*)d_in[2];
    const float* Ua = (const float*)d_in[3];
    const float* va = (const float*)d_in[4];
    float* out = (float*)d_out;

    cudaFuncSetAttribute(scores_mma_kernel,
                         cudaFuncAttributeMaxDynamicSharedMemorySize, SMEM_SZ);

    conv_U_kernel<<<(D_ * A_ / 4) / 256, 256>>>(Ua);
    conv_h_kernel<<<(int)(((size_t)B_ * T_ * D_ / 4) / 256), 256>>>(h);
    ws_kernel<<<dim3(A_ / 128, B_), 128>>>(s, Wa);
    scores_mma_kernel<<<(B_ * T_) / 128, 256, SMEM_SZ>>>(va);
    softmax_kernel<<<B_, 256>>>();
    context_part_kernel<<<dim3(D_ / 128, B_, 16), 128>>>(h);
    context_reduce_kernel<<<128, 256>>>(out);
}